// round 9
// baseline (speedup 1.0000x reference)
#include <cuda_runtime.h>
#include <cuda_fp16.h>

#define N_NODES 100000
#define SLOTS   128          // fixed adjacency slots per node (Poisson(64), tail-safe)
#define SSHIFT  7
#define FULL 0xffffffffu
#define NBLOCKS 592          // 4 blocks/SM, one wave; warps stride over nodes

// Static device scratch (no allocation allowed in kernel_launch).
__device__ __align__(128) int    g_cursor[N_NODES];
__device__ __align__(128) int    g_adj[N_NODES * SLOTS];   // 51.2 MB, L2-resident
__device__ __align__(128) __half g_xh[N_NODES * 16];       // padded input features, fp16 (3.2 MB)
__device__ __align__(128) __half g_h1h[N_NODES * 32];      // layer-1 output, fp16 (6.4 MB)

__device__ __forceinline__ __half2 as_h2(unsigned u) {
    return *reinterpret_cast<__half2*>(&u);
}

// ---------------------------------------------------------------------------
// K0: zero cursors, pad x [N,14] -> xh [N,16] fp16
// ---------------------------------------------------------------------------
__global__ void k_init(const float* __restrict__ x) {
    int idx = blockIdx.x * blockDim.x + threadIdx.x;
    int stride = gridDim.x * blockDim.x;
    for (int i = idx; i < N_NODES * 16; i += stride) {
        int node = i >> 4, f = i & 15;
        g_xh[i] = __float2half((f < 14) ? x[node * 14 + f] : 0.0f);
    }
    for (int i = idx; i < N_NODES; i += stride) g_cursor[i] = 0;
}

// ---------------------------------------------------------------------------
// K1: slotted scatter: adj[dst*128 + atomicAdd(cursor[dst])] = src
// ---------------------------------------------------------------------------
__global__ void k_scatter(const int* __restrict__ ei, int E) {
    int idx = blockIdx.x * blockDim.x + threadIdx.x;
    int stride = gridDim.x * blockDim.x;
    const int4* s4 = (const int4*)ei;
    const int4* d4 = (const int4*)(ei + E);
    int E4 = E >> 2;
    for (int i = idx; i < E4; i += stride) {
        int4 s = s4[i];
        int4 d = d4[i];
        int p;
        p = atomicAdd(&g_cursor[d.x], 1); if (p < SLOTS) g_adj[(d.x << SSHIFT) + p] = s.x;
        p = atomicAdd(&g_cursor[d.y], 1); if (p < SLOTS) g_adj[(d.y << SSHIFT) + p] = s.y;
        p = atomicAdd(&g_cursor[d.z], 1); if (p < SLOTS) g_adj[(d.z << SSHIFT) + p] = s.z;
        p = atomicAdd(&g_cursor[d.w], 1); if (p < SLOTS) g_adj[(d.w << SSHIFT) + p] = s.w;
    }
}

// ---------------------------------------------------------------------------
// K2: SAGE layer 1. Warp per node, warps stride over nodes so each block
// loads the smem weights once. 8 groups of 4 lanes; group loads 4 adj ids
// (broadcast int4); each lane loads one uint2 (8B) chunk of the 32B fp16
// x row -> 32 neighbors/iter. HADD2 pre-reduce, one fp32 flush per iter.
// ---------------------------------------------------------------------------
__global__ __launch_bounds__(256) void k_layer1(const float* __restrict__ W1l,
                                                const float* __restrict__ b1,
                                                const float* __restrict__ W1r) {
    __shared__ float2 sW[14 * 32];     // (wl, wr) pairs
    __shared__ float  sM[8][16];       // per warp: feature sums
    __shared__ float2 sP[8][16];       // per warp: (mean, xv)
    __shared__ float  sb[32];

    int tid = threadIdx.x;
    for (int i = tid; i < 14 * 32; i += 256)
        sW[i] = make_float2(W1l[i], W1r[i]);
    if (tid < 32) sb[tid] = b1[tid];
    __syncthreads();

    int warp = tid >> 5, lane = tid & 31;
    int q = lane >> 2, c = lane & 3;   // group (0..7), uint2 chunk (0..3)

    const int4*  adj4 = (const int4*)g_adj;
    const uint2* x2   = (const uint2*)g_xh;   // row = 4 uint2

    const int wstride = NBLOCKS * 8;
    for (int node = blockIdx.x * 8 + warp; node < N_NODES; node += wstride) {
        int deg = min(g_cursor[node], SLOTS);
        int base = node << 5;              // int4 index into adjacency row

        float fx0 = 0.f, fx1 = 0.f, fx2 = 0.f, fx3 = 0.f;
        int nfull = deg >> 5;
        for (int it = 0; it < nfull; it++) {
            int4 nb = adj4[base + (it << 3) + q];
            uint2 r0 = x2[nb.x * 4 + c];
            uint2 r1 = x2[nb.y * 4 + c];
            uint2 r2 = x2[nb.z * 4 + c];
            uint2 r3 = x2[nb.w * 4 + c];
            __half2 a0 = __hadd2(__hadd2(as_h2(r0.x), as_h2(r1.x)),
                                 __hadd2(as_h2(r2.x), as_h2(r3.x)));
            __half2 a1 = __hadd2(__hadd2(as_h2(r0.y), as_h2(r1.y)),
                                 __hadd2(as_h2(r2.y), as_h2(r3.y)));
            float2 f0 = __half22float2(a0);
            float2 f1 = __half22float2(a1);
            fx0 += f0.x; fx1 += f0.y; fx2 += f1.x; fx3 += f1.y;
        }
        int tb = nfull << 5;
        if (tb < deg) {                    // tail (<32 remaining), predicated per id
            int4 nb = adj4[base + (nfull << 3) + q];
            int t = tb + (q << 2);
            int ids[4] = {nb.x, nb.y, nb.z, nb.w};
            #pragma unroll
            for (int r = 0; r < 4; r++) {
                if (t + r < deg) {
                    uint2 v = x2[ids[r] * 4 + c];
                    float2 f0 = __half22float2(as_h2(v.x));
                    float2 f1 = __half22float2(as_h2(v.y));
                    fx0 += f0.x; fx1 += f0.y; fx2 += f1.x; fx3 += f1.y;
                }
            }
        }

        // reduce over 8 groups (lane bits 2..4)
        #pragma unroll
        for (int off = 4; off <= 16; off <<= 1) {
            fx0 += __shfl_xor_sync(FULL, fx0, off);
            fx1 += __shfl_xor_sync(FULL, fx1, off);
            fx2 += __shfl_xor_sync(FULL, fx2, off);
            fx3 += __shfl_xor_sync(FULL, fx3, off);
        }
        if (lane < 4)   // lane == c -> features 4c..4c+3
            *(float4*)&sM[warp][lane << 2] = make_float4(fx0, fx1, fx2, fx3);
        __syncwarp();

        float inv = 1.0f / (float)max(deg, 1);
        if (lane < 16) {
            float mean = sM[warp][lane] * inv;
            float xv = __half2float(g_xh[node * 16 + lane]);
            sP[warp][lane] = make_float2(mean, xv);
        }
        __syncwarp();

        float out = sb[lane];
        #pragma unroll
        for (int ff = 0; ff < 14; ff++) {
            float2 w = sW[ff * 32 + lane];
            float2 p = sP[warp][ff];
            out += p.x * w.x + p.y * w.y;
        }

        float ss = out * out;
        #pragma unroll
        for (int off = 16; off; off >>= 1) ss += __shfl_xor_sync(FULL, ss, off);
        float norm = fmaxf(sqrtf(ss), 1e-12f);
        out = fmaxf(out / norm, 0.0f);   // relu(normalize(out))

        g_h1h[node * 32 + lane] = __float2half(out);
        __syncwarp();
    }
}

// ---------------------------------------------------------------------------
// K3: SAGE layer 2 + final linear. Warp per node with node-striding (weights
// loaded once per block). 8 groups of 4 lanes; each lane loads one uint4
// (16B) chunk of the 64B fp16 h1 row -> 32 neighbors/iter. HADD2 pre-reduce,
// fp32 flush per iter.
// ---------------------------------------------------------------------------
__global__ __launch_bounds__(256) void k_layer2(const float* __restrict__ W2l,
                                                const float* __restrict__ b2,
                                                const float* __restrict__ W2r,
                                                const float* __restrict__ Wlin,
                                                const float* __restrict__ blin,
                                                float* __restrict__ outp) {
    __shared__ float2 sW[32 * 32];     // (wl, wr) pairs, 8 KB
    __shared__ float  sM[8][32];       // per warp: feature sums
    __shared__ float2 sP[8][32];       // per warp: (mean, hv)
    __shared__ float  sb[32];
    __shared__ float2 sLin[32];
    __shared__ float2 sblin;

    int tid = threadIdx.x;
    for (int i = tid; i < 32 * 32; i += 256)
        sW[i] = make_float2(W2l[i], W2r[i]);
    if (tid < 32) { sb[tid] = b2[tid]; sLin[tid] = ((const float2*)Wlin)[tid]; }
    if (tid == 0) sblin = *(const float2*)blin;
    __syncthreads();

    int warp = tid >> 5, lane = tid & 31;
    int q = lane >> 2, c = lane & 3;   // group (0..7), uint4 chunk (0..3)

    const int4*  adj4 = (const int4*)g_adj;
    const uint4* h4   = (const uint4*)g_h1h;   // row = 4 uint4

    const int wstride = NBLOCKS * 8;
    for (int node = blockIdx.x * 8 + warp; node < N_NODES; node += wstride) {
        int deg = min(g_cursor[node], SLOTS);
        int base = node << 5;

        float fx0 = 0.f, fx1 = 0.f, fx2 = 0.f, fx3 = 0.f;
        float fx4 = 0.f, fx5 = 0.f, fx6 = 0.f, fx7 = 0.f;
        int nfull = deg >> 5;
        for (int it = 0; it < nfull; it++) {
            int4 nb = adj4[base + (it << 3) + q];
            uint4 r0 = h4[nb.x * 4 + c];
            uint4 r1 = h4[nb.y * 4 + c];
            uint4 r2 = h4[nb.z * 4 + c];
            uint4 r3 = h4[nb.w * 4 + c];
            __half2 a0 = __hadd2(__hadd2(as_h2(r0.x), as_h2(r1.x)),
                                 __hadd2(as_h2(r2.x), as_h2(r3.x)));
            __half2 a1 = __hadd2(__hadd2(as_h2(r0.y), as_h2(r1.y)),
                                 __hadd2(as_h2(r2.y), as_h2(r3.y)));
            __half2 a2 = __hadd2(__hadd2(as_h2(r0.z), as_h2(r1.z)),
                                 __hadd2(as_h2(r2.z), as_h2(r3.z)));
            __half2 a3 = __hadd2(__hadd2(as_h2(r0.w), as_h2(r1.w)),
                                 __hadd2(as_h2(r2.w), as_h2(r3.w)));
            float2 f0 = __half22float2(a0);
            float2 f1 = __half22float2(a1);
            float2 f2 = __half22float2(a2);
            float2 f3 = __half22float2(a3);
            fx0 += f0.x; fx1 += f0.y; fx2 += f1.x; fx3 += f1.y;
            fx4 += f2.x; fx5 += f2.y; fx6 += f3.x; fx7 += f3.y;
        }
        int tb = nfull << 5;
        if (tb < deg) {                    // tail (<32 remaining), predicated per id
            int4 nb = adj4[base + (nfull << 3) + q];
            int t = tb + (q << 2);
            int ids[4] = {nb.x, nb.y, nb.z, nb.w};
            #pragma unroll
            for (int r = 0; r < 4; r++) {
                if (t + r < deg) {
                    uint4 v = h4[ids[r] * 4 + c];
                    float2 f0 = __half22float2(as_h2(v.x));
                    float2 f1 = __half22float2(as_h2(v.y));
                    float2 f2 = __half22float2(as_h2(v.z));
                    float2 f3 = __half22float2(as_h2(v.w));
                    fx0 += f0.x; fx1 += f0.y; fx2 += f1.x; fx3 += f1.y;
                    fx4 += f2.x; fx5 += f2.y; fx6 += f3.x; fx7 += f3.y;
                }
            }
        }

        // reduce over 8 groups (lane bits 2..4)
        #pragma unroll
        for (int off = 4; off <= 16; off <<= 1) {
            fx0 += __shfl_xor_sync(FULL, fx0, off);
            fx1 += __shfl_xor_sync(FULL, fx1, off);
            fx2 += __shfl_xor_sync(FULL, fx2, off);
            fx3 += __shfl_xor_sync(FULL, fx3, off);
            fx4 += __shfl_xor_sync(FULL, fx4, off);
            fx5 += __shfl_xor_sync(FULL, fx5, off);
            fx6 += __shfl_xor_sync(FULL, fx6, off);
            fx7 += __shfl_xor_sync(FULL, fx7, off);
        }
        if (lane < 4) {   // lane == c -> features 8c..8c+7
            *(float4*)&sM[warp][(lane << 3) + 0] = make_float4(fx0, fx1, fx2, fx3);
            *(float4*)&sM[warp][(lane << 3) + 4] = make_float4(fx4, fx5, fx6, fx7);
        }
        __syncwarp();

        float inv = 1.0f / (float)max(deg, 1);
        {
            float mean = sM[warp][lane] * inv;
            float hv = __half2float(g_h1h[node * 32 + lane]);
            sP[warp][lane] = make_float2(mean, hv);
        }
        __syncwarp();

        float out = sb[lane];
        #pragma unroll
        for (int ff = 0; ff < 32; ff++) {
            float2 w = sW[ff * 32 + lane];
            float2 p = sP[warp][ff];
            out += p.x * w.x + p.y * w.y;
        }

        float ss = out * out;
        #pragma unroll
        for (int off = 16; off; off >>= 1) ss += __shfl_xor_sync(FULL, ss, off);
        float norm = fmaxf(sqrtf(ss), 1e-12f);
        out = fmaxf(out / norm, 0.0f);

        // final linear [32 -> 2]
        float2 wlin = sLin[lane];
        float c0 = out * wlin.x;
        float c1 = out * wlin.y;
        #pragma unroll
        for (int off = 16; off; off >>= 1) {
            c0 += __shfl_xor_sync(FULL, c0, off);
            c1 += __shfl_xor_sync(FULL, c1, off);
        }
        if (lane == 0)
            ((float2*)outp)[node] = make_float2(c0 + sblin.x, c1 + sblin.y);
        __syncwarp();
    }
}

// ---------------------------------------------------------------------------
// Launch
// ---------------------------------------------------------------------------
extern "C" void kernel_launch(void* const* d_in, const int* in_sizes, int n_in,
                              void* d_out, int out_size) {
    const float* x    = (const float*)d_in[0];
    const int*   ei   = (const int*)d_in[1];
    const float* W1l  = (const float*)d_in[2];
    const float* b1   = (const float*)d_in[3];
    const float* W1r  = (const float*)d_in[4];
    const float* W2l  = (const float*)d_in[5];
    const float* b2   = (const float*)d_in[6];
    const float* W2r  = (const float*)d_in[7];
    const float* Wlin = (const float*)d_in[8];
    const float* blin = (const float*)d_in[9];
    float* out = (float*)d_out;

    int E = in_sizes[1] / 2;   // edge_index is [2, E]
    int E4 = E / 4;

    k_init<<<2048, 256>>>(x);
    k_scatter<<<(E4 + 255) / 256, 256>>>(ei, E);

    k_layer1<<<NBLOCKS, 256>>>(W1l, b1, W1r);
    k_layer2<<<NBLOCKS, 256>>>(W2l, b2, W2r, Wlin, blin, out);
}

// round 10
// speedup vs baseline: 1.0479x; 1.0479x over previous
#include <cuda_runtime.h>
#include <cuda_fp16.h>

#define N_NODES 100000
#define SLOTS   128          // fixed adjacency slots per node (Poisson(64), tail-safe)
#define SSHIFT  7
#define FULL 0xffffffffu
#define NBLK_L  1184         // layer kernels: warps stride over nodes

// Static device scratch (no allocation allowed in kernel_launch).
__device__ __align__(128) int    g_cursor[N_NODES];
__device__ __align__(128) int    g_adj[N_NODES * SLOTS];   // 51.2 MB, L2-resident
__device__ __align__(128) __half g_xh[N_NODES * 16];       // padded input features, fp16 (3.2 MB)
__device__ __align__(128) __half g_h1h[N_NODES * 32];      // layer-1 output, fp16 (6.4 MB)

__device__ __forceinline__ __half2 as_h2(unsigned u) {
    return *reinterpret_cast<__half2*>(&u);
}

// packed fp32x2 FMA: acc = a*b + acc (element-wise on both lanes)
__device__ __forceinline__ void fma2(float2& acc, float2 a, float2 b) {
    unsigned long long A = *reinterpret_cast<unsigned long long*>(&a);
    unsigned long long B = *reinterpret_cast<unsigned long long*>(&b);
    unsigned long long C = *reinterpret_cast<unsigned long long*>(&acc);
    asm("fma.rn.f32x2 %0, %1, %2, %0;" : "+l"(C) : "l"(A), "l"(B));
    acc = *reinterpret_cast<float2*>(&C);
}

// ---------------------------------------------------------------------------
// K0: zero cursors, pad x [N,14] -> xh [N,16] fp16
// ---------------------------------------------------------------------------
__global__ void k_init(const float* __restrict__ x) {
    int idx = blockIdx.x * blockDim.x + threadIdx.x;
    int stride = gridDim.x * blockDim.x;
    for (int i = idx; i < N_NODES * 16; i += stride) {
        int node = i >> 4, f = i & 15;
        g_xh[i] = __float2half((f < 14) ? x[node * 14 + f] : 0.0f);
    }
    for (int i = idx; i < N_NODES; i += stride) g_cursor[i] = 0;
}

// ---------------------------------------------------------------------------
// K1: slotted scatter, unrolled x2 (8 edges / iter, 8 independent atomics)
// ---------------------------------------------------------------------------
__global__ void k_scatter(const int* __restrict__ ei, int E) {
    int idx = blockIdx.x * blockDim.x + threadIdx.x;
    int stride = gridDim.x * blockDim.x;
    const int4* s4 = (const int4*)ei;
    const int4* d4 = (const int4*)(ei + E);
    int E4 = E >> 2;
    int nPairs = E4 >> 1;
    for (int i = idx; i < nPairs; i += stride) {
        int4 sA = s4[2 * i], sB = s4[2 * i + 1];
        int4 dA = d4[2 * i], dB = d4[2 * i + 1];
        int p;
        p = atomicAdd(&g_cursor[dA.x], 1); if (p < SLOTS) g_adj[(dA.x << SSHIFT) + p] = sA.x;
        p = atomicAdd(&g_cursor[dA.y], 1); if (p < SLOTS) g_adj[(dA.y << SSHIFT) + p] = sA.y;
        p = atomicAdd(&g_cursor[dA.z], 1); if (p < SLOTS) g_adj[(dA.z << SSHIFT) + p] = sA.z;
        p = atomicAdd(&g_cursor[dA.w], 1); if (p < SLOTS) g_adj[(dA.w << SSHIFT) + p] = sA.w;
        p = atomicAdd(&g_cursor[dB.x], 1); if (p < SLOTS) g_adj[(dB.x << SSHIFT) + p] = sB.x;
        p = atomicAdd(&g_cursor[dB.y], 1); if (p < SLOTS) g_adj[(dB.y << SSHIFT) + p] = sB.y;
        p = atomicAdd(&g_cursor[dB.z], 1); if (p < SLOTS) g_adj[(dB.z << SSHIFT) + p] = sB.z;
        p = atomicAdd(&g_cursor[dB.w], 1); if (p < SLOTS) g_adj[(dB.w << SSHIFT) + p] = sB.w;
    }
    // tail (E4 odd)
    for (int i = (nPairs << 1) + idx; i < E4; i += stride) {
        int4 s = s4[i];
        int4 d = d4[i];
        int p;
        p = atomicAdd(&g_cursor[d.x], 1); if (p < SLOTS) g_adj[(d.x << SSHIFT) + p] = s.x;
        p = atomicAdd(&g_cursor[d.y], 1); if (p < SLOTS) g_adj[(d.y << SSHIFT) + p] = s.y;
        p = atomicAdd(&g_cursor[d.z], 1); if (p < SLOTS) g_adj[(d.z << SSHIFT) + p] = s.z;
        p = atomicAdd(&g_cursor[d.w], 1); if (p < SLOTS) g_adj[(d.w << SSHIFT) + p] = s.w;
    }
}

// ---------------------------------------------------------------------------
// K2: SAGE layer 1. Warp per node, node-striding. 8 groups of 4 lanes; group
// loads 4 adj ids (broadcast int4); lane loads one uint2 (8B) chunk of the
// 32B fp16 x row -> 32 neighbors/iter. Weights live in REGISTERS as packed
// half2 (wl,wr); transform uses fma.rn.f32x2 with float2 accumulator.
// ---------------------------------------------------------------------------
__global__ __launch_bounds__(256) void k_layer1(const float* __restrict__ W1l,
                                                const float* __restrict__ b1,
                                                const float* __restrict__ W1r) {
    __shared__ float  sM[8][16];       // per warp: feature sums
    __shared__ float2 sP[8][16];       // per warp: (mean, xv)

    int tid = threadIdx.x;
    int warp = tid >> 5, lane = tid & 31;
    int q = lane >> 2, c = lane & 3;   // group (0..7), uint2 chunk (0..3)

    // per-thread weight column, packed fp16 (loaded once per kernel)
    __half2 w1h[14];
    #pragma unroll
    for (int ff = 0; ff < 14; ff++)
        w1h[ff] = __floats2half2_rn(W1l[ff * 32 + lane], W1r[ff * 32 + lane]);
    float bias = b1[lane];

    const int4*  adj4 = (const int4*)g_adj;
    const uint2* x2   = (const uint2*)g_xh;   // row = 4 uint2

    const int wstride = NBLK_L * 8;
    for (int node = blockIdx.x * 8 + warp; node < N_NODES; node += wstride) {
        int deg = min(g_cursor[node], SLOTS);
        int base = node << 5;              // int4 index into adjacency row

        float fx0 = 0.f, fx1 = 0.f, fx2 = 0.f, fx3 = 0.f;
        int nfull = deg >> 5;
        for (int it = 0; it < nfull; it++) {
            int4 nb = adj4[base + (it << 3) + q];
            uint2 r0 = x2[nb.x * 4 + c];
            uint2 r1 = x2[nb.y * 4 + c];
            uint2 r2 = x2[nb.z * 4 + c];
            uint2 r3 = x2[nb.w * 4 + c];
            __half2 a0 = __hadd2(__hadd2(as_h2(r0.x), as_h2(r1.x)),
                                 __hadd2(as_h2(r2.x), as_h2(r3.x)));
            __half2 a1 = __hadd2(__hadd2(as_h2(r0.y), as_h2(r1.y)),
                                 __hadd2(as_h2(r2.y), as_h2(r3.y)));
            float2 f0 = __half22float2(a0);
            float2 f1 = __half22float2(a1);
            fx0 += f0.x; fx1 += f0.y; fx2 += f1.x; fx3 += f1.y;
        }
        int tb = nfull << 5;
        if (tb < deg) {                    // tail (<32 remaining), predicated per id
            int4 nb = adj4[base + (nfull << 3) + q];
            int t = tb + (q << 2);
            int ids[4] = {nb.x, nb.y, nb.z, nb.w};
            #pragma unroll
            for (int r = 0; r < 4; r++) {
                if (t + r < deg) {
                    uint2 v = x2[ids[r] * 4 + c];
                    float2 f0 = __half22float2(as_h2(v.x));
                    float2 f1 = __half22float2(as_h2(v.y));
                    fx0 += f0.x; fx1 += f0.y; fx2 += f1.x; fx3 += f1.y;
                }
            }
        }

        // reduce over 8 groups (lane bits 2..4)
        #pragma unroll
        for (int off = 4; off <= 16; off <<= 1) {
            fx0 += __shfl_xor_sync(FULL, fx0, off);
            fx1 += __shfl_xor_sync(FULL, fx1, off);
            fx2 += __shfl_xor_sync(FULL, fx2, off);
            fx3 += __shfl_xor_sync(FULL, fx3, off);
        }
        if (lane < 4)   // lane == c -> features 4c..4c+3
            *(float4*)&sM[warp][lane << 2] = make_float4(fx0, fx1, fx2, fx3);
        __syncwarp();

        float inv = 1.0f / (float)max(deg, 1);
        if (lane < 16) {
            float mean = sM[warp][lane] * inv;
            float xv = __half2float(g_xh[node * 16 + lane]);
            sP[warp][lane] = make_float2(mean, xv);
        }
        __syncwarp();

        float2 o = make_float2(bias, 0.0f);
        #pragma unroll
        for (int ff = 0; ff < 14; ff++) {
            float2 w = __half22float2(w1h[ff]);
            float2 p = sP[warp][ff];       // broadcast LDS.64
            fma2(o, p, w);
        }
        float out = o.x + o.y;

        float ss = out * out;
        #pragma unroll
        for (int off = 16; off; off >>= 1) ss += __shfl_xor_sync(FULL, ss, off);
        float norm = fmaxf(sqrtf(ss), 1e-12f);
        out = fmaxf(out / norm, 0.0f);   // relu(normalize(out))

        g_h1h[node * 32 + lane] = __float2half(out);
        __syncwarp();
    }
}

// ---------------------------------------------------------------------------
// K3: SAGE layer 2 + final linear. Warp per node, node-striding. 8 groups of
// 4 lanes; lane loads one uint4 (16B) chunk of the 64B fp16 h1 row ->
// 32 neighbors/iter. Weights in REGISTERS as packed half2 (wl,wr).
// ---------------------------------------------------------------------------
__global__ __launch_bounds__(256) void k_layer2(const float* __restrict__ W2l,
                                                const float* __restrict__ b2,
                                                const float* __restrict__ W2r,
                                                const float* __restrict__ Wlin,
                                                const float* __restrict__ blin,
                                                float* __restrict__ outp) {
    __shared__ float  sM[8][32];       // per warp: feature sums
    __shared__ float2 sP[8][32];       // per warp: (mean, hv)

    int tid = threadIdx.x;
    int warp = tid >> 5, lane = tid & 31;
    int q = lane >> 2, c = lane & 3;   // group (0..7), uint4 chunk (0..3)

    // per-thread weight column, packed fp16 (loaded once per kernel)
    __half2 w2h[32];
    #pragma unroll
    for (int ff = 0; ff < 32; ff++)
        w2h[ff] = __floats2half2_rn(W2l[ff * 32 + lane], W2r[ff * 32 + lane]);
    float bias = b2[lane];
    float2 wlin = ((const float2*)Wlin)[lane];
    float2 bl = *(const float2*)blin;

    const int4*  adj4 = (const int4*)g_adj;
    const uint4* h4   = (const uint4*)g_h1h;   // row = 4 uint4

    const int wstride = NBLK_L * 8;
    for (int node = blockIdx.x * 8 + warp; node < N_NODES; node += wstride) {
        int deg = min(g_cursor[node], SLOTS);
        int base = node << 5;

        float fx0 = 0.f, fx1 = 0.f, fx2 = 0.f, fx3 = 0.f;
        float fx4 = 0.f, fx5 = 0.f, fx6 = 0.f, fx7 = 0.f;
        int nfull = deg >> 5;
        for (int it = 0; it < nfull; it++) {
            int4 nb = adj4[base + (it << 3) + q];
            uint4 r0 = h4[nb.x * 4 + c];
            uint4 r1 = h4[nb.y * 4 + c];
            uint4 r2 = h4[nb.z * 4 + c];
            uint4 r3 = h4[nb.w * 4 + c];
            __half2 a0 = __hadd2(__hadd2(as_h2(r0.x), as_h2(r1.x)),
                                 __hadd2(as_h2(r2.x), as_h2(r3.x)));
            __half2 a1 = __hadd2(__hadd2(as_h2(r0.y), as_h2(r1.y)),
                                 __hadd2(as_h2(r2.y), as_h2(r3.y)));
            __half2 a2 = __hadd2(__hadd2(as_h2(r0.z), as_h2(r1.z)),
                                 __hadd2(as_h2(r2.z), as_h2(r3.z)));
            __half2 a3 = __hadd2(__hadd2(as_h2(r0.w), as_h2(r1.w)),
                                 __hadd2(as_h2(r2.w), as_h2(r3.w)));
            float2 f0 = __half22float2(a0);
            float2 f1 = __half22float2(a1);
            float2 f2 = __half22float2(a2);
            float2 f3 = __half22float2(a3);
            fx0 += f0.x; fx1 += f0.y; fx2 += f1.x; fx3 += f1.y;
            fx4 += f2.x; fx5 += f2.y; fx6 += f3.x; fx7 += f3.y;
        }
        int tb = nfull << 5;
        if (tb < deg) {                    // tail (<32 remaining), predicated per id
            int4 nb = adj4[base + (nfull << 3) + q];
            int t = tb + (q << 2);
            int ids[4] = {nb.x, nb.y, nb.z, nb.w};
            #pragma unroll
            for (int r = 0; r < 4; r++) {
                if (t + r < deg) {
                    uint4 v = h4[ids[r] * 4 + c];
                    float2 f0 = __half22float2(as_h2(v.x));
                    float2 f1 = __half22float2(as_h2(v.y));
                    float2 f2 = __half22float2(as_h2(v.z));
                    float2 f3 = __half22float2(as_h2(v.w));
                    fx0 += f0.x; fx1 += f0.y; fx2 += f1.x; fx3 += f1.y;
                    fx4 += f2.x; fx5 += f2.y; fx6 += f3.x; fx7 += f3.y;
                }
            }
        }

        // reduce over 8 groups (lane bits 2..4)
        #pragma unroll
        for (int off = 4; off <= 16; off <<= 1) {
            fx0 += __shfl_xor_sync(FULL, fx0, off);
            fx1 += __shfl_xor_sync(FULL, fx1, off);
            fx2 += __shfl_xor_sync(FULL, fx2, off);
            fx3 += __shfl_xor_sync(FULL, fx3, off);
            fx4 += __shfl_xor_sync(FULL, fx4, off);
            fx5 += __shfl_xor_sync(FULL, fx5, off);
            fx6 += __shfl_xor_sync(FULL, fx6, off);
            fx7 += __shfl_xor_sync(FULL, fx7, off);
        }
        if (lane < 4) {   // lane == c -> features 8c..8c+7
            *(float4*)&sM[warp][(lane << 3) + 0] = make_float4(fx0, fx1, fx2, fx3);
            *(float4*)&sM[warp][(lane << 3) + 4] = make_float4(fx4, fx5, fx6, fx7);
        }
        __syncwarp();

        float inv = 1.0f / (float)max(deg, 1);
        {
            float mean = sM[warp][lane] * inv;
            float hv = __half2float(g_h1h[node * 32 + lane]);
            sP[warp][lane] = make_float2(mean, hv);
        }
        __syncwarp();

        float2 o = make_float2(bias, 0.0f);
        #pragma unroll
        for (int ff = 0; ff < 32; ff++) {
            float2 w = __half22float2(w2h[ff]);
            float2 p = sP[warp][ff];       // broadcast LDS.64
            fma2(o, p, w);
        }
        float out = o.x + o.y;

        float ss = out * out;
        #pragma unroll
        for (int off = 16; off; off >>= 1) ss += __shfl_xor_sync(FULL, ss, off);
        float norm = fmaxf(sqrtf(ss), 1e-12f);
        out = fmaxf(out / norm, 0.0f);

        // final linear [32 -> 2]
        float c0 = out * wlin.x;
        float c1 = out * wlin.y;
        #pragma unroll
        for (int off = 16; off; off >>= 1) {
            c0 += __shfl_xor_sync(FULL, c0, off);
            c1 += __shfl_xor_sync(FULL, c1, off);
        }
        if (lane == 0)
            ((float2*)outp)[node] = make_float2(c0 + bl.x, c1 + bl.y);
        __syncwarp();
    }
}

// ---------------------------------------------------------------------------
// Launch
// ---------------------------------------------------------------------------
extern "C" void kernel_launch(void* const* d_in, const int* in_sizes, int n_in,
                              void* d_out, int out_size) {
    const float* x    = (const float*)d_in[0];
    const int*   ei   = (const int*)d_in[1];
    const float* W1l  = (const float*)d_in[2];
    const float* b1   = (const float*)d_in[3];
    const float* W1r  = (const float*)d_in[4];
    const float* W2l  = (const float*)d_in[5];
    const float* b2   = (const float*)d_in[6];
    const float* W2r  = (const float*)d_in[7];
    const float* Wlin = (const float*)d_in[8];
    const float* blin = (const float*)d_in[9];
    float* out = (float*)d_out;

    int E = in_sizes[1] / 2;   // edge_index is [2, E]
    int nPairs = (E >> 2) >> 1;

    k_init<<<2048, 256>>>(x);
    k_scatter<<<(nPairs + 255) / 256, 256>>>(ei, E);

    k_layer1<<<NBLK_L, 256>>>(W1l, b1, W1r);
    k_layer2<<<NBLK_L, 256>>>(W2l, b2, W2r, Wlin, blin, out);
}

// round 11
// speedup vs baseline: 1.0726x; 1.0236x over previous
#include <cuda_runtime.h>
#include <cuda_fp16.h>

#define N_NODES 100000
#define SLOTS   128          // fixed adjacency slots per node (Poisson(64), tail-safe)
#define SSHIFT  7
#define FULL 0xffffffffu
#define NBLK_L  1184         // layer kernels: warps stride over nodes

// Static device scratch (no allocation allowed in kernel_launch).
__device__ __align__(128) int    g_cursor[N_NODES];
__device__ __align__(128) int    g_adj[N_NODES * SLOTS];   // 51.2 MB, L2-resident
__device__ __align__(128) __half g_xh[N_NODES * 16];       // padded input features, fp16 (3.2 MB)
__device__ __align__(128) __half g_h1h[N_NODES * 32];      // layer-1 output, fp16 (6.4 MB)

__device__ __forceinline__ __half2 as_h2(unsigned u) {
    return *reinterpret_cast<__half2*>(&u);
}

// packed fp32x2 FMA: acc = a*b + acc (element-wise on both lanes)
__device__ __forceinline__ void fma2(float2& acc, float2 a, float2 b) {
    unsigned long long A = *reinterpret_cast<unsigned long long*>(&a);
    unsigned long long B = *reinterpret_cast<unsigned long long*>(&b);
    unsigned long long C = *reinterpret_cast<unsigned long long*>(&acc);
    asm("fma.rn.f32x2 %0, %1, %2, %0;" : "+l"(C) : "l"(A), "l"(B));
    acc = *reinterpret_cast<float2*>(&C);
}

// ---------------------------------------------------------------------------
// K0: zero cursors, pad x [N,14] -> xh [N,16] fp16
// ---------------------------------------------------------------------------
__global__ void k_init(const float* __restrict__ x) {
    int idx = blockIdx.x * blockDim.x + threadIdx.x;
    int stride = gridDim.x * blockDim.x;
    for (int i = idx; i < N_NODES * 16; i += stride) {
        int node = i >> 4, f = i & 15;
        g_xh[i] = __float2half((f < 14) ? x[node * 14 + f] : 0.0f);
    }
    for (int i = idx; i < N_NODES; i += stride) g_cursor[i] = 0;
}

// ---------------------------------------------------------------------------
// K1: slotted scatter, unrolled x2 (8 edges / iter, 8 independent atomics)
// ---------------------------------------------------------------------------
__global__ void k_scatter(const int* __restrict__ ei, int E) {
    int idx = blockIdx.x * blockDim.x + threadIdx.x;
    int stride = gridDim.x * blockDim.x;
    const int4* s4 = (const int4*)ei;
    const int4* d4 = (const int4*)(ei + E);
    int E4 = E >> 2;
    int nPairs = E4 >> 1;
    for (int i = idx; i < nPairs; i += stride) {
        int4 sA = s4[2 * i], sB = s4[2 * i + 1];
        int4 dA = d4[2 * i], dB = d4[2 * i + 1];
        int p;
        p = atomicAdd(&g_cursor[dA.x], 1); if (p < SLOTS) g_adj[(dA.x << SSHIFT) + p] = sA.x;
        p = atomicAdd(&g_cursor[dA.y], 1); if (p < SLOTS) g_adj[(dA.y << SSHIFT) + p] = sA.y;
        p = atomicAdd(&g_cursor[dA.z], 1); if (p < SLOTS) g_adj[(dA.z << SSHIFT) + p] = sA.z;
        p = atomicAdd(&g_cursor[dA.w], 1); if (p < SLOTS) g_adj[(dA.w << SSHIFT) + p] = sA.w;
        p = atomicAdd(&g_cursor[dB.x], 1); if (p < SLOTS) g_adj[(dB.x << SSHIFT) + p] = sB.x;
        p = atomicAdd(&g_cursor[dB.y], 1); if (p < SLOTS) g_adj[(dB.y << SSHIFT) + p] = sB.y;
        p = atomicAdd(&g_cursor[dB.z], 1); if (p < SLOTS) g_adj[(dB.z << SSHIFT) + p] = sB.z;
        p = atomicAdd(&g_cursor[dB.w], 1); if (p < SLOTS) g_adj[(dB.w << SSHIFT) + p] = sB.w;
    }
    // tail (E4 odd)
    for (int i = (nPairs << 1) + idx; i < E4; i += stride) {
        int4 s = s4[i];
        int4 d = d4[i];
        int p;
        p = atomicAdd(&g_cursor[d.x], 1); if (p < SLOTS) g_adj[(d.x << SSHIFT) + p] = s.x;
        p = atomicAdd(&g_cursor[d.y], 1); if (p < SLOTS) g_adj[(d.y << SSHIFT) + p] = s.y;
        p = atomicAdd(&g_cursor[d.z], 1); if (p < SLOTS) g_adj[(d.z << SSHIFT) + p] = s.z;
        p = atomicAdd(&g_cursor[d.w], 1); if (p < SLOTS) g_adj[(d.w << SSHIFT) + p] = s.w;
    }
}

// ---------------------------------------------------------------------------
// K2: SAGE layer 1. Warp per node, node-striding. 8 groups of 4 lanes; group
// loads 4 adj ids (broadcast int4); lane loads one uint2 (8B) chunk of the
// 32B fp16 x row -> 32 neighbors/iter. Weights in SMEM as packed half2
// (wl,wr); transform: LDS.32 weight pair + broadcast LDS.64 p + fma.rn.f32x2.
// ---------------------------------------------------------------------------
__global__ __launch_bounds__(256) void k_layer1(const float* __restrict__ W1l,
                                                const float* __restrict__ b1,
                                                const float* __restrict__ W1r) {
    __shared__ __half2 sW[14 * 32];    // (wl, wr) fp16 pairs, 1.75 KB
    __shared__ float   sb[32];
    __shared__ float   sM[8][16];      // per warp: feature sums
    __shared__ float2  sP[8][16];      // per warp: (mean, xv)

    int tid = threadIdx.x;
    for (int i = tid; i < 14 * 32; i += 256)
        sW[i] = __floats2half2_rn(W1l[i], W1r[i]);
    if (tid < 32) sb[tid] = b1[tid];
    __syncthreads();

    int warp = tid >> 5, lane = tid & 31;
    int q = lane >> 2, c = lane & 3;   // group (0..7), uint2 chunk (0..3)
    float bias = sb[lane];

    const int4*  adj4 = (const int4*)g_adj;
    const uint2* x2   = (const uint2*)g_xh;   // row = 4 uint2

    const int wstride = NBLK_L * 8;
    for (int node = blockIdx.x * 8 + warp; node < N_NODES; node += wstride) {
        int deg = min(g_cursor[node], SLOTS);
        int base = node << 5;              // int4 index into adjacency row

        float fx0 = 0.f, fx1 = 0.f, fx2 = 0.f, fx3 = 0.f;
        int nfull = deg >> 5;
        for (int it = 0; it < nfull; it++) {
            int4 nb = adj4[base + (it << 3) + q];
            uint2 r0 = x2[nb.x * 4 + c];
            uint2 r1 = x2[nb.y * 4 + c];
            uint2 r2 = x2[nb.z * 4 + c];
            uint2 r3 = x2[nb.w * 4 + c];
            __half2 a0 = __hadd2(__hadd2(as_h2(r0.x), as_h2(r1.x)),
                                 __hadd2(as_h2(r2.x), as_h2(r3.x)));
            __half2 a1 = __hadd2(__hadd2(as_h2(r0.y), as_h2(r1.y)),
                                 __hadd2(as_h2(r2.y), as_h2(r3.y)));
            float2 f0 = __half22float2(a0);
            float2 f1 = __half22float2(a1);
            fx0 += f0.x; fx1 += f0.y; fx2 += f1.x; fx3 += f1.y;
        }
        int tb = nfull << 5;
        if (tb < deg) {                    // tail (<32 remaining), predicated per id
            int4 nb = adj4[base + (nfull << 3) + q];
            int t = tb + (q << 2);
            int ids[4] = {nb.x, nb.y, nb.z, nb.w};
            #pragma unroll
            for (int r = 0; r < 4; r++) {
                if (t + r < deg) {
                    uint2 v = x2[ids[r] * 4 + c];
                    float2 f0 = __half22float2(as_h2(v.x));
                    float2 f1 = __half22float2(as_h2(v.y));
                    fx0 += f0.x; fx1 += f0.y; fx2 += f1.x; fx3 += f1.y;
                }
            }
        }

        // reduce over 8 groups (lane bits 2..4)
        #pragma unroll
        for (int off = 4; off <= 16; off <<= 1) {
            fx0 += __shfl_xor_sync(FULL, fx0, off);
            fx1 += __shfl_xor_sync(FULL, fx1, off);
            fx2 += __shfl_xor_sync(FULL, fx2, off);
            fx3 += __shfl_xor_sync(FULL, fx3, off);
        }
        if (lane < 4)   // lane == c -> features 4c..4c+3
            *(float4*)&sM[warp][lane << 2] = make_float4(fx0, fx1, fx2, fx3);
        __syncwarp();

        float inv = 1.0f / (float)max(deg, 1);
        if (lane < 16) {
            float mean = sM[warp][lane] * inv;
            float xv = __half2float(g_xh[node * 16 + lane]);
            sP[warp][lane] = make_float2(mean, xv);
        }
        __syncwarp();

        float2 o = make_float2(bias, 0.0f);
        #pragma unroll
        for (int ff = 0; ff < 14; ff++) {
            float2 w = __half22float2(sW[ff * 32 + lane]);  // LDS.32
            float2 p = sP[warp][ff];                        // broadcast LDS.64
            fma2(o, p, w);
        }
        float out = o.x + o.y;

        float ss = out * out;
        #pragma unroll
        for (int off = 16; off; off >>= 1) ss += __shfl_xor_sync(FULL, ss, off);
        float norm = fmaxf(sqrtf(ss), 1e-12f);
        out = fmaxf(out / norm, 0.0f);   // relu(normalize(out))

        g_h1h[node * 32 + lane] = __float2half(out);
        __syncwarp();
    }
}

// ---------------------------------------------------------------------------
// K3: SAGE layer 2 + final linear. Warp per node, node-striding. 8 groups of
// 4 lanes; lane loads one uint4 (16B) chunk of the 64B fp16 h1 row ->
// 32 neighbors/iter. Weights in SMEM as packed half2 (wl,wr).
// ---------------------------------------------------------------------------
__global__ __launch_bounds__(256) void k_layer2(const float* __restrict__ W2l,
                                                const float* __restrict__ b2,
                                                const float* __restrict__ W2r,
                                                const float* __restrict__ Wlin,
                                                const float* __restrict__ blin,
                                                float* __restrict__ outp) {
    __shared__ __half2 sW[32 * 32];    // (wl, wr) fp16 pairs, 4 KB
    __shared__ float   sb[32];
    __shared__ float2  sLin[32];
    __shared__ float   sM[8][32];      // per warp: feature sums
    __shared__ float2  sP[8][32];      // per warp: (mean, hv)

    int tid = threadIdx.x;
    for (int i = tid; i < 32 * 32; i += 256)
        sW[i] = __floats2half2_rn(W2l[i], W2r[i]);
    if (tid < 32) { sb[tid] = b2[tid]; sLin[tid] = ((const float2*)Wlin)[tid]; }
    __syncthreads();

    int warp = tid >> 5, lane = tid & 31;
    int q = lane >> 2, c = lane & 3;   // group (0..7), uint4 chunk (0..3)
    float bias = sb[lane];
    float2 wlin = sLin[lane];
    float2 bl = *(const float2*)blin;

    const int4*  adj4 = (const int4*)g_adj;
    const uint4* h4   = (const uint4*)g_h1h;   // row = 4 uint4

    const int wstride = NBLK_L * 8;
    for (int node = blockIdx.x * 8 + warp; node < N_NODES; node += wstride) {
        int deg = min(g_cursor[node], SLOTS);
        int base = node << 5;

        float fx0 = 0.f, fx1 = 0.f, fx2 = 0.f, fx3 = 0.f;
        float fx4 = 0.f, fx5 = 0.f, fx6 = 0.f, fx7 = 0.f;
        int nfull = deg >> 5;
        for (int it = 0; it < nfull; it++) {
            int4 nb = adj4[base + (it << 3) + q];
            uint4 r0 = h4[nb.x * 4 + c];
            uint4 r1 = h4[nb.y * 4 + c];
            uint4 r2 = h4[nb.z * 4 + c];
            uint4 r3 = h4[nb.w * 4 + c];
            __half2 a0 = __hadd2(__hadd2(as_h2(r0.x), as_h2(r1.x)),
                                 __hadd2(as_h2(r2.x), as_h2(r3.x)));
            __half2 a1 = __hadd2(__hadd2(as_h2(r0.y), as_h2(r1.y)),
                                 __hadd2(as_h2(r2.y), as_h2(r3.y)));
            __half2 a2 = __hadd2(__hadd2(as_h2(r0.z), as_h2(r1.z)),
                                 __hadd2(as_h2(r2.z), as_h2(r3.z)));
            __half2 a3 = __hadd2(__hadd2(as_h2(r0.w), as_h2(r1.w)),
                                 __hadd2(as_h2(r2.w), as_h2(r3.w)));
            float2 f0 = __half22float2(a0);
            float2 f1 = __half22float2(a1);
            float2 f2 = __half22float2(a2);
            float2 f3 = __half22float2(a3);
            fx0 += f0.x; fx1 += f0.y; fx2 += f1.x; fx3 += f1.y;
            fx4 += f2.x; fx5 += f2.y; fx6 += f3.x; fx7 += f3.y;
        }
        int tb = nfull << 5;
        if (tb < deg) {                    // tail (<32 remaining), predicated per id
            int4 nb = adj4[base + (nfull << 3) + q];
            int t = tb + (q << 2);
            int ids[4] = {nb.x, nb.y, nb.z, nb.w};
            #pragma unroll
            for (int r = 0; r < 4; r++) {
                if (t + r < deg) {
                    uint4 v = h4[ids[r] * 4 + c];
                    float2 f0 = __half22float2(as_h2(v.x));
                    float2 f1 = __half22float2(as_h2(v.y));
                    float2 f2 = __half22float2(as_h2(v.z));
                    float2 f3 = __half22float2(as_h2(v.w));
                    fx0 += f0.x; fx1 += f0.y; fx2 += f1.x; fx3 += f1.y;
                    fx4 += f2.x; fx5 += f2.y; fx6 += f3.x; fx7 += f3.y;
                }
            }
        }

        // reduce over 8 groups (lane bits 2..4)
        #pragma unroll
        for (int off = 4; off <= 16; off <<= 1) {
            fx0 += __shfl_xor_sync(FULL, fx0, off);
            fx1 += __shfl_xor_sync(FULL, fx1, off);
            fx2 += __shfl_xor_sync(FULL, fx2, off);
            fx3 += __shfl_xor_sync(FULL, fx3, off);
            fx4 += __shfl_xor_sync(FULL, fx4, off);
            fx5 += __shfl_xor_sync(FULL, fx5, off);
            fx6 += __shfl_xor_sync(FULL, fx6, off);
            fx7 += __shfl_xor_sync(FULL, fx7, off);
        }
        if (lane < 4) {   // lane == c -> features 8c..8c+7
            *(float4*)&sM[warp][(lane << 3) + 0] = make_float4(fx0, fx1, fx2, fx3);
            *(float4*)&sM[warp][(lane << 3) + 4] = make_float4(fx4, fx5, fx6, fx7);
        }
        __syncwarp();

        float inv = 1.0f / (float)max(deg, 1);
        {
            float mean = sM[warp][lane] * inv;
            float hv = __half2float(g_h1h[node * 32 + lane]);
            sP[warp][lane] = make_float2(mean, hv);
        }
        __syncwarp();

        float2 o = make_float2(bias, 0.0f);
        #pragma unroll
        for (int ff = 0; ff < 32; ff++) {
            float2 w = __half22float2(sW[ff * 32 + lane]);  // LDS.32
            float2 p = sP[warp][ff];                        // broadcast LDS.64
            fma2(o, p, w);
        }
        float out = o.x + o.y;

        float ss = out * out;
        #pragma unroll
        for (int off = 16; off; off >>= 1) ss += __shfl_xor_sync(FULL, ss, off);
        float norm = fmaxf(sqrtf(ss), 1e-12f);
        out = fmaxf(out / norm, 0.0f);

        // final linear [32 -> 2]
        float c0 = out * wlin.x;
        float c1 = out * wlin.y;
        #pragma unroll
        for (int off = 16; off; off >>= 1) {
            c0 += __shfl_xor_sync(FULL, c0, off);
            c1 += __shfl_xor_sync(FULL, c1, off);
        }
        if (lane == 0)
            ((float2*)outp)[node] = make_float2(c0 + bl.x, c1 + bl.y);
        __syncwarp();
    }
}

// ---------------------------------------------------------------------------
// Launch
// ---------------------------------------------------------------------------
extern "C" void kernel_launch(void* const* d_in, const int* in_sizes, int n_in,
                              void* d_out, int out_size) {
    const float* x    = (const float*)d_in[0];
    const int*   ei   = (const int*)d_in[1];
    const float* W1l  = (const float*)d_in[2];
    const float* b1   = (const float*)d_in[3];
    const float* W1r  = (const float*)d_in[4];
    const float* W2l  = (const float*)d_in[5];
    const float* b2   = (const float*)d_in[6];
    const float* W2r  = (const float*)d_in[7];
    const float* Wlin = (const float*)d_in[8];
    const float* blin = (const float*)d_in[9];
    float* out = (float*)d_out;

    int E = in_sizes[1] / 2;   // edge_index is [2, E]
    int nPairs = (E >> 2) >> 1;

    k_init<<<2048, 256>>>(x);
    k_scatter<<<(nPairs + 255) / 256, 256>>>(ei, E);

    k_layer1<<<NBLK_L, 256>>>(W1l, b1, W1r);
    k_layer2<<<NBLK_L, 256>>>(W2l, b2, W2r, Wlin, blin, out);
}